// round 3
// baseline (speedup 1.0000x reference)
#include <cuda_runtime.h>
#include <cstdint>
#include <cstddef>

// Problem dims
#define NB   128     // batch
#define NT   256     // time steps
#define HD   1024    // hidden
#define IN   150     // input feature (J*D)
#define INP  160     // padded input feature (16B-aligned rows)
#define NC   60      // classes
#define G4   4096    // 4*HD

// Tile config
#define TM   64      // batch tile
#define TU   8       // hidden-unit tile
#define TN   32      // gate rows per CTA = 4 gates * TU
#define TK   16
#define NTHREADS 128

typedef unsigned long long ull;

// ---------------- persistent device state (sanctioned scratch) ----------------
__device__ float g_h1[2][NB * HD];
__device__ float g_h2[2][NB * HD];
__device__ float g_c1[NB * HD];
__device__ float g_c2[NB * HD];
__device__ float g_bias1[G4];
__device__ float g_bias2[G4];
__device__ float g_xp[NT * NB * INP];    // x repacked: [T][B][INP], zero-padded
__device__ float g_wih1p[G4 * INP];      // Wih1 padded: [4096][INP]

__device__ __forceinline__ float sigf(float x) { return 1.0f / (1.0f + expf(-x)); }

// packed fp32x2 FMA: d.lo += a.lo*b.lo ; d.hi += a.hi*b.hi  (full fp32 per lane)
__device__ __forceinline__ void ffma2(ull& d, ull a, ull b) {
    asm("fma.rn.f32x2 %0, %1, %2, %0;" : "+l"(d) : "l"(a), "l"(b));
}

// ---------------- one-time prep kernels ----------------
__global__ void init_kernel(const float* __restrict__ h1, const float* __restrict__ c1,
                            const float* __restrict__ h2, const float* __restrict__ c2,
                            const float* __restrict__ bih1, const float* __restrict__ bhh1,
                            const float* __restrict__ bih2, const float* __restrict__ bhh2) {
    int i = blockIdx.x * blockDim.x + threadIdx.x;
    if (i < NB * HD) {
        g_h1[0][i] = h1[i];
        g_c1[i]    = c1[i];
        g_h2[0][i] = h2[i];
        g_c2[i]    = c2[i];
    }
    if (i < G4) {
        g_bias1[i] = bih1[i] + bhh1[i];
        g_bias2[i] = bih2[i] + bhh2[i];
    }
}

__global__ void repack_x_kernel(const float* __restrict__ x) {
    int idx = blockIdx.x * blockDim.x + threadIdx.x;   // over NT*NB*INP
    if (idx >= NT * NB * INP) return;
    int c = idx % INP;
    int r = idx / INP;
    int b = r % NB;
    int t = r / NB;
    float v = 0.0f;
    if (c < IN) v = x[((size_t)b * NT + t) * IN + c];
    g_xp[((size_t)t * NB + b) * INP + c] = v;
}

__global__ void pad_wih1_kernel(const float* __restrict__ Wih1) {
    int idx = blockIdx.x * blockDim.x + threadIdx.x;   // over G4*INP
    if (idx >= G4 * INP) return;
    int c = idx % INP;
    int r = idx / INP;
    g_wih1p[idx] = (c < IN) ? Wih1[(size_t)r * IN + c] : 0.0f;
}

// ---------------- fused LSTM step (one layer per launch) ----------------
// phase 0: gates1 = h1[cur]@Whh1^T + xp_t@Wih1p^T + bias1 -> (h1[cur^1], c1)
// phase 1: gates2 = h1[cur^1]@Wih2^T + h2[cur]@Whh2^T + bias2 -> (h2[cur^1], c2)
__global__ __launch_bounds__(NTHREADS)
void lstm_step_kernel(int t, int phase,
                      const float* __restrict__ Whh1,
                      const float* __restrict__ Wih2, const float* __restrict__ Whh2) {
    __shared__ float As[2][TK][TM + 4];     // [k][m]
    __shared__ ull   Bs2[2][TK][TN + 2];    // [k][n] duplicated {b,b}
    __shared__ float Gs[TN][TM + 1];

    const int cur = t & 1;
    const float *A0, *A1, *W0, *W1, *bias;
    float *cst, *hout;
    int lda1, K0, K1;
    if (phase == 0) {
        A0 = g_h1[cur];                       K0 = HD;  W0 = Whh1;
        A1 = g_xp + (size_t)t * NB * INP;     K1 = INP; W1 = g_wih1p; lda1 = INP;
        bias = g_bias1; cst = g_c1; hout = g_h1[cur ^ 1];
    } else {
        A0 = g_h1[cur ^ 1];                   K0 = HD;  W0 = Wih2;
        A1 = g_h2[cur];                       K1 = HD;  W1 = Whh2;    lda1 = HD;
        bias = g_bias2; cst = g_c2; hout = g_h2[cur ^ 1];
    }

    const int tid = threadIdx.x;
    const int tx  = tid & 15;    // m direction: 16 threads x 4 m
    const int ty  = tid >> 4;    // n direction: 8 threads x 4 n
    const int m0  = blockIdx.x * TM;
    const int u0  = blockIdx.y * TU;

    // global->smem load assignments
    const int arow  = tid >> 1;            // 0..63 (batch row within tile)
    const int akoff = (tid & 1) * 8;       // k offsets [akoff, akoff+8)
    const int brow  = tid >> 2;            // 0..31 (gate row within tile)
    const int bkoff = (tid & 3) * 4;       // k offsets [bkoff, bkoff+4)
    const int brW   = (brow >> 3) * HD + u0 + (brow & 7);  // global W row

    ull acc[2][4];   // [m-pair][n], each packs 2 fp32 (m = tx*4 + 2i + lane)
#pragma unroll
    for (int i = 0; i < 2; i++)
#pragma unroll
        for (int j = 0; j < 4; j++) acc[i][j] = 0ull;

    const int nk0 = K0 / TK;
    const int nk1 = K1 / TK;
    const int ntiles = nk0 + nk1;

    float ra[8], rb[4];

    auto fetch = [&](int tile) {
        const float* A; const float* W; int lda, K, k0;
        if (tile < nk0) { A = A0; W = W0; lda = HD;   K = K0; k0 = tile * TK; }
        else            { A = A1; W = W1; lda = lda1; K = K1; k0 = (tile - nk0) * TK; }
        const float4* ap = (const float4*)(A + (size_t)(m0 + arow) * lda + k0 + akoff);
        float4 v0 = ap[0];
        float4 v1 = ap[1];
        ra[0] = v0.x; ra[1] = v0.y; ra[2] = v0.z; ra[3] = v0.w;
        ra[4] = v1.x; ra[5] = v1.y; ra[6] = v1.z; ra[7] = v1.w;
        float4 w = *(const float4*)(W + (size_t)brW * K + k0 + bkoff);
        rb[0] = w.x; rb[1] = w.y; rb[2] = w.z; rb[3] = w.w;
    };

    auto store = [&](int buf) {
#pragma unroll
        for (int i = 0; i < 8; i++) As[buf][akoff + i][arow] = ra[i];
#pragma unroll
        for (int i = 0; i < 4; i++) {
            unsigned u = __float_as_uint(rb[i]);
            Bs2[buf][bkoff + i][brow] = ((ull)u << 32) | u;   // duplicate {b,b}
        }
    };

    fetch(0);
    store(0);
    __syncthreads();

    int buf = 0;
    for (int tile = 0; tile < ntiles; tile++) {
        if (tile + 1 < ntiles) fetch(tile + 1);
#pragma unroll
        for (int kk = 0; kk < TK; kk++) {
            ulonglong2 a01 = *(const ulonglong2*)&As[buf][kk][tx * 4];   // 2 m-pairs
            ulonglong2 b01 = *(const ulonglong2*)&Bs2[buf][kk][ty * 4];  // n0,n1 dup
            ulonglong2 b23 = *(const ulonglong2*)&Bs2[buf][kk][ty * 4 + 2];
            ffma2(acc[0][0], a01.x, b01.x);
            ffma2(acc[0][1], a01.x, b01.y);
            ffma2(acc[0][2], a01.x, b23.x);
            ffma2(acc[0][3], a01.x, b23.y);
            ffma2(acc[1][0], a01.y, b01.x);
            ffma2(acc[1][1], a01.y, b01.y);
            ffma2(acc[1][2], a01.y, b23.x);
            ffma2(acc[1][3], a01.y, b23.y);
        }
        if (tile + 1 < ntiles) {
            store(buf ^ 1);
            __syncthreads();
            buf ^= 1;
        }
    }
    __syncthreads();

    // stage gates (+bias) to smem, grouped for cell update
#pragma unroll
    for (int j = 0; j < 4; j++) {
        int nl = ty * 4 + j;
        int g  = nl >> 3;
        int du = nl & 7;
        float bv = bias[g * HD + u0 + du];
#pragma unroll
        for (int i = 0; i < 2; i++) {
            ull v = acc[i][j];
            Gs[nl][tx * 4 + 2 * i]     = __uint_as_float((unsigned)v) + bv;
            Gs[nl][tx * 4 + 2 * i + 1] = __uint_as_float((unsigned)(v >> 32)) + bv;
        }
    }
    __syncthreads();

    // cell update: TM*TU = 512 cells, 4 per thread
#pragma unroll
    for (int r = 0; r < (TM * TU) / NTHREADS; r++) {
        int idx = tid + r * NTHREADS;
        int u   = idx >> 6;       // 0..7
        int ml  = idx & 63;       // 0..63
        float ig = Gs[u][ml];
        float fg = Gs[8 + u][ml];
        float gg = Gs[16 + u][ml];
        float og = Gs[24 + u][ml];
        int off = (m0 + ml) * HD + (u0 + u);
        float c  = cst[off];
        float cn = sigf(fg) * c + sigf(ig) * tanhf(gg);
        cst[off]  = cn;
        hout[off] = sigf(og) * tanhf(cn);
    }
}

// ---------------- final FC: out = h2 @ Wfc^T + bfc ----------------
__global__ void fc_kernel(const float* __restrict__ Wfc, const float* __restrict__ bfc,
                          float* __restrict__ out) {
    int b = blockIdx.x;
    int c = blockIdx.y;
    int lane = threadIdx.x;
    const float* h = &g_h2[0][b * HD];
    const float* w = Wfc + (size_t)c * HD;
    float s = 0.0f;
    for (int k = lane; k < HD; k += 32) s += h[k] * w[k];
#pragma unroll
    for (int o = 16; o > 0; o >>= 1) s += __shfl_xor_sync(0xFFFFFFFFu, s, o);
    if (lane == 0) out[b * NC + c] = s + bfc[c];
}

// ---------------- launch ----------------
extern "C" void kernel_launch(void* const* d_in, const int* in_sizes, int n_in,
                              void* d_out, int out_size) {
    (void)in_sizes; (void)n_in; (void)out_size;
    const float* x    = (const float*)d_in[0];
    const float* h1   = (const float*)d_in[1];
    const float* c1   = (const float*)d_in[2];
    const float* h2   = (const float*)d_in[3];
    const float* c2   = (const float*)d_in[4];
    const float* Wih1 = (const float*)d_in[5];
    const float* Whh1 = (const float*)d_in[6];
    const float* bih1 = (const float*)d_in[7];
    const float* bhh1 = (const float*)d_in[8];
    const float* Wih2 = (const float*)d_in[9];
    const float* Whh2 = (const float*)d_in[10];
    const float* bih2 = (const float*)d_in[11];
    const float* bhh2 = (const float*)d_in[12];
    const float* Wfc  = (const float*)d_in[13];
    const float* bfc  = (const float*)d_in[14];
    float* out = (float*)d_out;

    init_kernel<<<(NB * HD + 255) / 256, 256>>>(h1, c1, h2, c2, bih1, bhh1, bih2, bhh2);
    repack_x_kernel<<<(NT * NB * INP + 255) / 256, 256>>>(x);
    pad_wih1_kernel<<<(G4 * INP + 255) / 256, 256>>>(Wih1);

    dim3 grid(NB / TM, HD / TU);   // (2, 128)
    for (int t = 0; t < NT; t++) {
        lstm_step_kernel<<<grid, NTHREADS>>>(t, 0, Whh1, Wih2, Whh2);
        lstm_step_kernel<<<grid, NTHREADS>>>(t, 1, Whh1, Wih2, Whh2);
    }

    fc_kernel<<<dim3(NB, NC), 32>>>(Wfc, bfc, out);
}

// round 7
// speedup vs baseline: 1.7492x; 1.7492x over previous
#include <cuda_runtime.h>
#include <cuda_bf16.h>
#include <cstdint>
#include <cstddef>

// Problem dims
#define NB   128     // batch
#define NT   256     // time steps
#define HD   1024    // hidden
#define IN   150     // input feature (J*D)
#define INP  192     // padded input feature (multiple of 64)
#define NC   60      // classes
#define G4   4096    // 4*HD

#define HDE  (3*HD)   // 3072: extended K for hidden ([hi|hi|lo] on A side)
#define INE  (3*INP)  // 576:  extended K for input

// GEMM tiling: CTA 64(M) x 64(N), 4 warps of 32x32, K-tile 64
#define KT      64
#define NSTAGE  3
#define AROWB   144            // padded smem row: 64 bf16 + 8 pad = 144 B
#define ATILEB  (64 * AROWB)   // 9216 B
#define STAGEB  (2 * ATILEB)   // A + B per stage = 18432 B
#define GS_STRIDE 65
#define SMEM_DYN (NSTAGE * STAGEB + 64 * GS_STRIDE * 4 + 64 * 4)  // 72192

// ---------------- persistent device state ----------------
__device__ __nv_bfloat16 g_h1e[2][NB * HDE];
__device__ __nv_bfloat16 g_h2e[2][NB * HDE];
__device__ float g_c1[NB * HD];
__device__ float g_c2[NB * HD];
__device__ float g_bias1e[G4];
__device__ float g_bias2e[G4];
__device__ __nv_bfloat16 g_whh1e[G4 * HDE];
__device__ __nv_bfloat16 g_wih2e[G4 * HDE];
__device__ __nv_bfloat16 g_whh2e[G4 * HDE];
__device__ __nv_bfloat16 g_wih1e[G4 * INE];
__device__ __nv_bfloat16 g_xe[NT * NB * INE];

// ---------------- PTX helpers (family-safe: sm_80-level instructions only) ----
__device__ __forceinline__ uint32_t smem_u32(const void* p) {
    uint32_t a;
    asm("{ .reg .u64 t; cvta.to.shared.u64 t, %1; cvt.u32.u64 %0, t; }" : "=r"(a) : "l"(p));
    return a;
}
__device__ __forceinline__ void cpasync16(uint32_t dst, const void* src) {
    asm volatile("cp.async.cg.shared.global [%0], [%1], 16;" :: "r"(dst), "l"(src));
}
#define CP_COMMIT() asm volatile("cp.async.commit_group;" ::: "memory")
#define CP_WAIT(n)  asm volatile("cp.async.wait_group %0;" :: "n"(n) : "memory")

__device__ __forceinline__ void ldsm4(uint32_t* r, uint32_t addr) {
    asm volatile("ldmatrix.sync.aligned.m8n8.x4.shared.b16 {%0,%1,%2,%3}, [%4];"
                 : "=r"(r[0]), "=r"(r[1]), "=r"(r[2]), "=r"(r[3]) : "r"(addr));
}
__device__ __forceinline__ void mma16816(float* d, const uint32_t* a, const uint32_t* b) {
    asm volatile(
        "mma.sync.aligned.m16n8k16.row.col.f32.bf16.bf16.f32 "
        "{%0,%1,%2,%3}, {%4,%5,%6,%7}, {%8,%9}, {%0,%1,%2,%3};"
        : "+f"(d[0]), "+f"(d[1]), "+f"(d[2]), "+f"(d[3])
        : "r"(a[0]), "r"(a[1]), "r"(a[2]), "r"(a[3]), "r"(b[0]), "r"(b[1]));
}

__device__ __forceinline__ float sigf(float x) { return 1.0f / (1.0f + __expf(-x)); }
__device__ __forceinline__ float tanh_f(float x) { return 2.0f / (1.0f + __expf(-2.0f * x)) - 1.0f; }

// ---------------- prep kernels ----------------
// W[4096][K] (orig row g*HD+u) -> ext rows n=u*4+g, cols [hi(KP)|lo(KP)|hi(KP)]
__global__ void prep_weight_ext(const float* __restrict__ W, __nv_bfloat16* __restrict__ out,
                                int K, int KP) {
    int idx = blockIdx.x * blockDim.x + threadIdx.x;
    if (idx >= G4 * KP) return;
    int n = idx / KP, k = idx % KP;
    int g = n & 3, u = n >> 2;
    float v = (k < K) ? W[(size_t)(g * HD + u) * K + k] : 0.0f;
    __nv_bfloat16 hi = __float2bfloat16(v);
    __nv_bfloat16 lo = __float2bfloat16(v - __bfloat162float(hi));
    size_t base = (size_t)n * 3 * KP;
    out[base + k] = hi;
    out[base + KP + k] = lo;
    out[base + 2 * KP + k] = hi;
}

// x[b][t][150] -> xe[t][b][576] = [hi|hi|lo]
__global__ void prep_x_ext(const float* __restrict__ x) {
    int idx = blockIdx.x * blockDim.x + threadIdx.x;
    if (idx >= NT * NB * INP) return;
    int k = idx % INP;
    int r = idx / INP;
    int b = r % NB, t = r / NB;
    float v = (k < IN) ? x[((size_t)b * NT + t) * IN + k] : 0.0f;
    __nv_bfloat16 hi = __float2bfloat16(v);
    __nv_bfloat16 lo = __float2bfloat16(v - __bfloat162float(hi));
    size_t base = ((size_t)t * NB + b) * INE;
    g_xe[base + k] = hi;
    g_xe[base + INP + k] = hi;
    g_xe[base + 2 * INP + k] = lo;
}

__global__ void prep_state(const float* __restrict__ h1, const float* __restrict__ c1,
                           const float* __restrict__ h2, const float* __restrict__ c2,
                           const float* __restrict__ bih1, const float* __restrict__ bhh1,
                           const float* __restrict__ bih2, const float* __restrict__ bhh2) {
    int i = blockIdx.x * blockDim.x + threadIdx.x;
    if (i < NB * HD) {
        int m = i / HD, u = i % HD;
        float v1 = h1[i], v2 = h2[i];
        __nv_bfloat16 h1hi = __float2bfloat16(v1);
        __nv_bfloat16 h1lo = __float2bfloat16(v1 - __bfloat162float(h1hi));
        __nv_bfloat16 h2hi = __float2bfloat16(v2);
        __nv_bfloat16 h2lo = __float2bfloat16(v2 - __bfloat162float(h2hi));
        size_t base = (size_t)m * HDE;
        g_h1e[0][base + u] = h1hi; g_h1e[0][base + HD + u] = h1hi; g_h1e[0][base + 2 * HD + u] = h1lo;
        g_h2e[0][base + u] = h2hi; g_h2e[0][base + HD + u] = h2hi; g_h2e[0][base + 2 * HD + u] = h2lo;
        g_c1[i] = c1[i];
        g_c2[i] = c2[i];
    }
    if (i < G4) {
        int g = i & 3, u = i >> 2;
        int r = g * HD + u;
        g_bias1e[i] = bih1[r] + bhh1[r];
        g_bias2e[i] = bih2[r] + bhh2[r];
    }
}

// ---------------- fused LSTM phase (mma.sync tensor cores) ----------------
// grid = (64, 2): blockIdx.x = n-tile (64 gate-ext rows), blockIdx.y = m-tile (64 batch)
__global__ void __launch_bounds__(128)
lstm_phase_mma(int t, int phase) {
    extern __shared__ __align__(16) char sm[];
    const uint32_t SB = smem_u32(sm);
    float* Gs    = (float*)(sm + NSTAGE * STAGEB);
    float* biasS = Gs + 64 * GS_STRIDE;

    const int tid  = threadIdx.x;
    const int wid  = tid >> 5;
    const int lane = tid & 31;
    const int m0 = blockIdx.y * 64;
    const int n0 = blockIdx.x * 64;
    const int cur = t & 1;

    // segment setup
    const __nv_bfloat16 *A0, *B0, *A1, *B1;
    const float* biasE;
    float* cst;
    __nv_bfloat16* houtE;
    int ld1, K1;
    if (phase == 0) {
        A0 = g_h1e[cur];      B0 = g_whh1e;
        A1 = g_xe + (size_t)t * NB * INE;  B1 = g_wih1e;
        ld1 = INE; K1 = INE;
        biasE = g_bias1e; cst = g_c1; houtE = g_h1e[cur ^ 1];
    } else {
        A0 = g_h1e[cur ^ 1];  B0 = g_wih2e;
        A1 = g_h2e[cur];      B1 = g_whh2e;
        ld1 = HDE; K1 = HDE;
        biasE = g_bias2e; cst = g_c2; houtE = g_h2e[cur ^ 1];
    }
    const int T0 = HDE / KT;          // 48
    const int T1 = K1 / KT;           // 9 or 48
    const int TT = T0 + T1;

    if (tid < 64) biasS[tid] = biasE[n0 + tid];

    // global->smem load assignment: row = tid>>1 (0..63), half-row = (tid&1)*32 elems
    const int arow = tid >> 1;
    const int acolB = (tid & 1) * 64;   // bytes within row (32 bf16)

    auto load_tile = [&](int tile, int stage) {
        const __nv_bfloat16 *A, *B;
        int ld, kb;
        if (tile < T0) { A = A0; B = B0; ld = HDE; kb = tile * KT; }
        else           { A = A1; B = B1; ld = ld1; kb = (tile - T0) * KT; }
        const char* ap = (const char*)(A + (size_t)(m0 + arow) * ld + kb) + acolB;
        const char* bp = (const char*)(B + (size_t)(n0 + arow) * ld + kb) + acolB;
        uint32_t da = SB + stage * STAGEB + arow * AROWB + acolB;
        uint32_t db = da + ATILEB;
#pragma unroll
        for (int i = 0; i < 4; i++) {
            cpasync16(da + i * 16, ap + i * 16);
            cpasync16(db + i * 16, bp + i * 16);
        }
        CP_COMMIT();
    };

    // ldmatrix per-lane offsets
    // A (x4, non-trans): matrix order = (m0-7,k0-7), (m8-15,k0-7), (m0-7,k8-15), (m8-15,k8-15)
    const int wr = wid >> 1;      // m half
    const int wc = wid & 1;       // n half
    const int grp = lane >> 3, lr = lane & 7;
    uint32_t aoff[2], boff[2];
#pragma unroll
    for (int mi = 0; mi < 2; mi++)
        aoff[mi] = (uint32_t)((wr * 32 + mi * 16 + lr + (grp & 1) * 8) * AROWB + (grp >> 1) * 16);
    // B (x4, non-trans; smem is [n][k] which IS col-major B):
    // matrix order = (n0-7,k0-7), (n0-7,k8-15), (n8-15,k0-7), (n8-15,k8-15)
#pragma unroll
    for (int nc = 0; nc < 2; nc++)
        boff[nc] = (uint32_t)((wc * 32 + nc * 16 + lr + (grp >> 1) * 8) * AROWB + (grp & 1) * 16) + ATILEB;

    float d[2][4][4];
#pragma unroll
    for (int mi = 0; mi < 2; mi++)
#pragma unroll
        for (int nj = 0; nj < 4; nj++)
#pragma unroll
            for (int q = 0; q < 4; q++) d[mi][nj][q] = 0.0f;

    // prologue
    load_tile(0, 0);
    load_tile(1, 1);

    for (int c = 0; c < TT; c++) {
        const int s = c % NSTAGE;
        // Tail-correct drain: on the last tile no newer group exists, so
        // wait_group 1 would let the current tile still be in flight.
        if (c + 1 < TT) { CP_WAIT(1); } else { CP_WAIT(0); }
        __syncthreads();

        const uint32_t sb = SB + s * STAGEB;
#pragma unroll
        for (int kk = 0; kk < 4; kk++) {
            uint32_t a0r[4], a1r[4], b0r[4], b1r[4];
            ldsm4(a0r, sb + aoff[0] + kk * 32);
            ldsm4(a1r, sb + aoff[1] + kk * 32);
            ldsm4(b0r, sb + boff[0] + kk * 32);
            ldsm4(b1r, sb + boff[1] + kk * 32);
            mma16816(d[0][0], a0r, b0r + 0);
            mma16816(d[0][1], a0r, b0r + 2);
            mma16816(d[0][2], a0r, b1r + 0);
            mma16816(d[0][3], a0r, b1r + 2);
            mma16816(d[1][0], a1r, b0r + 0);
            mma16816(d[1][1], a1r, b0r + 2);
            mma16816(d[1][2], a1r, b1r + 0);
            mma16816(d[1][3], a1r, b1r + 2);
        }
        __syncthreads();
        if (c + 2 < TT) load_tile(c + 2, (c + 2) % NSTAGE);
    }

    // epilogue: acc -> Gs [n][m]
#pragma unroll
    for (int mi = 0; mi < 2; mi++) {
#pragma unroll
        for (int nj = 0; nj < 4; nj++) {
            int r0 = wr * 32 + mi * 16 + (lane >> 2);
            int cb = wc * 32 + nj * 8 + (lane & 3) * 2;
            Gs[cb * GS_STRIDE + r0]           = d[mi][nj][0];
            Gs[(cb + 1) * GS_STRIDE + r0]     = d[mi][nj][1];
            Gs[cb * GS_STRIDE + r0 + 8]       = d[mi][nj][2];
            Gs[(cb + 1) * GS_STRIDE + r0 + 8] = d[mi][nj][3];
        }
    }
    __syncthreads();

    // cell update: 64 m x 16 u = 1024 cells, 8 per thread
    const int ubase = n0 >> 2;
#pragma unroll
    for (int r = 0; r < 8; r++) {
        int idx = tid + r * 128;
        int ml = idx & 63;
        int u  = idx >> 6;      // 0..15
        int nb = u * 4;
        float gi_ = Gs[(nb + 0) * GS_STRIDE + ml] + biasS[nb + 0];
        float gf_ = Gs[(nb + 1) * GS_STRIDE + ml] + biasS[nb + 1];
        float gg_ = Gs[(nb + 2) * GS_STRIDE + ml] + biasS[nb + 2];
        float go_ = Gs[(nb + 3) * GS_STRIDE + ml] + biasS[nb + 3];
        int ug = ubase + u;
        int m  = m0 + ml;
        int off = m * HD + ug;
        float cv = cst[off];
        float cn = sigf(gf_) * cv + sigf(gi_) * tanh_f(gg_);
        cst[off] = cn;
        float h = sigf(go_) * tanh_f(cn);
        __nv_bfloat16 hi = __float2bfloat16(h);
        __nv_bfloat16 lo = __float2bfloat16(h - __bfloat162float(hi));
        size_t hb = (size_t)m * HDE;
        houtE[hb + ug] = hi;
        houtE[hb + HD + ug] = hi;
        houtE[hb + 2 * HD + ug] = lo;
    }
}

// ---------------- final FC: out = h2 @ Wfc^T + bfc ----------------
__global__ void fc_kernel(const float* __restrict__ Wfc, const float* __restrict__ bfc,
                          float* __restrict__ out) {
    int b = blockIdx.x;
    int c = blockIdx.y;
    int lane = threadIdx.x;
    const __nv_bfloat16* he = &g_h2e[0][(size_t)b * HDE];
    const float* w = Wfc + (size_t)c * HD;
    float s = 0.0f;
    for (int k = lane; k < HD; k += 32) {
        float h = __bfloat162float(he[k]) + __bfloat162float(he[2 * HD + k]);
        s += h * w[k];
    }
#pragma unroll
    for (int o = 16; o > 0; o >>= 1) s += __shfl_xor_sync(0xFFFFFFFFu, s, o);
    if (lane == 0) out[b * NC + c] = s + bfc[c];
}

// ---------------- launch ----------------
extern "C" void kernel_launch(void* const* d_in, const int* in_sizes, int n_in,
                              void* d_out, int out_size) {
    (void)in_sizes; (void)n_in; (void)out_size;
    const float* x    = (const float*)d_in[0];
    const float* h1   = (const float*)d_in[1];
    const float* c1   = (const float*)d_in[2];
    const float* h2   = (const float*)d_in[3];
    const float* c2   = (const float*)d_in[4];
    const float* Wih1 = (const float*)d_in[5];
    const float* Whh1 = (const float*)d_in[6];
    const float* bih1 = (const float*)d_in[7];
    const float* bhh1 = (const float*)d_in[8];
    const float* Wih2 = (const float*)d_in[9];
    const float* Whh2 = (const float*)d_in[10];
    const float* bih2 = (const float*)d_in[11];
    const float* bhh2 = (const float*)d_in[12];
    const float* Wfc  = (const float*)d_in[13];
    const float* bfc  = (const float*)d_in[14];
    float* out = (float*)d_out;

    static int smem_set = 0;
    if (!smem_set) {
        cudaFuncSetAttribute(lstm_phase_mma, cudaFuncAttributeMaxDynamicSharedMemorySize, SMEM_DYN);
        smem_set = 1;
    }

    // one-time prep
    prep_state<<<(NB * HD + 255) / 256, 256>>>(h1, c1, h2, c2, bih1, bhh1, bih2, bhh2);
    __nv_bfloat16* whh1e; cudaGetSymbolAddress((void**)&whh1e, g_whh1e);
    __nv_bfloat16* wih2e; cudaGetSymbolAddress((void**)&wih2e, g_wih2e);
    __nv_bfloat16* whh2e; cudaGetSymbolAddress((void**)&whh2e, g_whh2e);
    __nv_bfloat16* wih1e; cudaGetSymbolAddress((void**)&wih1e, g_wih1e);
    prep_weight_ext<<<(G4 * HD + 255) / 256, 256>>>(Whh1, whh1e, HD, HD);
    prep_weight_ext<<<(G4 * HD + 255) / 256, 256>>>(Wih2, wih2e, HD, HD);
    prep_weight_ext<<<(G4 * HD + 255) / 256, 256>>>(Whh2, whh2e, HD, HD);
    prep_weight_ext<<<(G4 * INP + 255) / 256, 256>>>(Wih1, wih1e, IN, INP);
    prep_x_ext<<<(NT * NB * INP + 255) / 256, 256>>>(x);

    // recurrence: 2 launches per step
    dim3 grid(G4 / 64, NB / 64);   // (64, 2)
    for (int t = 0; t < NT; t++) {
        lstm_phase_mma<<<grid, 128, SMEM_DYN>>>(t, 0);
        lstm_phase_mma<<<grid, 128, SMEM_DYN>>>(t, 1);
    }

    fc_kernel<<<dim3(NB, NC), 32>>>(Wfc, bfc, out);
}